// round 1
// baseline (speedup 1.0000x reference)
#include <cuda_runtime.h>
#include <cstdint>

#define B_  4
#define S_  2048
#define DM_ 512
#define H_  8
#define D_  64

// ---------------- scratch (device globals; no allocation allowed) ----------------
__device__ float g_q[B_ * S_ * DM_];
__device__ float g_k[B_ * S_ * DM_];
__device__ float g_v[B_ * S_ * DM_];
__device__ float g_ctx[B_ * S_ * DM_];
__device__ float g_part[B_ * 16 * DM_];
__device__ float g_vmean[B_ * DM_];

// ---------------- SGEMM: C[M,512] = A[M,512] @ W[512,512] + bias ----------------
// 128x128 tile, BK=8, 256 threads, 8x8 per thread, fp32.
__global__ __launch_bounds__(256) void sgemm_bias(const float* __restrict__ A,
                                                  const float* __restrict__ W,
                                                  const float* __restrict__ bias,
                                                  float* __restrict__ C) {
    __shared__ float As[8 * 132];
    __shared__ float Bs[8 * 132];

    const int tid = threadIdx.x;
    const int bm = blockIdx.x * 128;
    const int bn = blockIdx.y * 128;
    const int tx = tid & 15;   // -> 8 cols
    const int ty = tid >> 4;   // -> 8 rows

    const int a_row = tid >> 1;         // 0..127
    const int a_k   = (tid & 1) * 4;    // 0 or 4
    const int b_k   = tid >> 5;         // 0..7
    const int b_n   = (tid & 31) * 4;   // 0..124

    const float* Aptr = A + (size_t)(bm + a_row) * 512 + a_k;
    const float* Wptr = W + (size_t)b_k * 512 + bn + b_n;

    float4 ra = *(const float4*)(Aptr);
    float4 rb = *(const float4*)(Wptr);

    float acc[8][8];
#pragma unroll
    for (int i = 0; i < 8; i++)
#pragma unroll
        for (int j = 0; j < 8; j++) acc[i][j] = 0.f;

    for (int kt = 0; kt < 64; kt++) {
        As[(a_k + 0) * 132 + a_row] = ra.x;
        As[(a_k + 1) * 132 + a_row] = ra.y;
        As[(a_k + 2) * 132 + a_row] = ra.z;
        As[(a_k + 3) * 132 + a_row] = ra.w;
        *(float4*)&Bs[b_k * 132 + b_n] = rb;
        __syncthreads();

        if (kt < 63) {
            ra = *(const float4*)(Aptr + (kt + 1) * 8);
            rb = *(const float4*)(Wptr + (size_t)(kt + 1) * 8 * 512);
        }

#pragma unroll
        for (int kk = 0; kk < 8; kk++) {
            float a[8], b[8];
            *(float4*)(a)     = *(const float4*)&As[kk * 132 + ty * 8];
            *(float4*)(a + 4) = *(const float4*)&As[kk * 132 + ty * 8 + 4];
            *(float4*)(b)     = *(const float4*)&Bs[kk * 132 + tx * 8];
            *(float4*)(b + 4) = *(const float4*)&Bs[kk * 132 + tx * 8 + 4];
#pragma unroll
            for (int i = 0; i < 8; i++)
#pragma unroll
                for (int j = 0; j < 8; j++) acc[i][j] += a[i] * b[j];
        }
        __syncthreads();
    }

#pragma unroll
    for (int i = 0; i < 8; i++) {
        const int m = bm + ty * 8 + i;
        float* crow = C + (size_t)m * 512 + bn + tx * 8;
        const float* br = bias + bn + tx * 8;
        float4 o0, o1;
        o0.x = acc[i][0] + br[0]; o0.y = acc[i][1] + br[1];
        o0.z = acc[i][2] + br[2]; o0.w = acc[i][3] + br[3];
        o1.x = acc[i][4] + br[4]; o1.y = acc[i][5] + br[5];
        o1.z = acc[i][6] + br[6]; o1.w = acc[i][7] + br[7];
        *(float4*)(crow)     = o0;
        *(float4*)(crow + 4) = o1;
    }
}

// ---------------- V mean over full sequence (for fully-masked rows) ----------------
__global__ void vmean_partial(const float* __restrict__ V, float* __restrict__ part) {
    const int b = blockIdx.y, sc = blockIdx.x, c = threadIdx.x;
    const float* p = V + ((size_t)b * S_ + sc * 128) * DM_ + c;
    float s = 0.f;
#pragma unroll 8
    for (int t = 0; t < 128; t++) s += p[(size_t)t * DM_];
    part[((size_t)b * 16 + sc) * DM_ + c] = s;
}

__global__ void vmean_final(const float* __restrict__ part, float* __restrict__ vm) {
    const int b = blockIdx.x, c = threadIdx.x;
    const float* p = part + (size_t)b * 16 * DM_ + c;
    float s = 0.f;
#pragma unroll
    for (int t = 0; t < 16; t++) s += p[(size_t)t * DM_];
    vm[b * DM_ + c] = s * (1.0f / 2048.0f);
}

// ---------------- banded attention ----------------
// block = (64 queries) x (head) x (batch); 256 threads.
// smem: Qs[64][65] (d-major), Ks[64][65] (d-major, per 64-key chunk),
//       Ss[64][325] (energies/probs for full 320-key span), Vs[320][65], invl[64]
#define ATT_SMEM_FLOATS (64 * 65 + 64 * 65 + 64 * 325 + 320 * 65 + 64)
#define ATT_SMEM_BYTES  (ATT_SMEM_FLOATS * 4)

__global__ __launch_bounds__(256, 1) void attn_kernel(const float* __restrict__ Q,
                                                      const float* __restrict__ K,
                                                      const float* __restrict__ V,
                                                      const float* __restrict__ VMEAN,
                                                      const int* __restrict__ XLEN,
                                                      float* __restrict__ CTX) {
    extern __shared__ float sm[];
    float* Qs   = sm;                    // 64*65
    float* Ks   = Qs + 64 * 65;          // 64*65
    float* Ss   = Ks + 64 * 65;          // 64*325
    float* Vs   = Ss + 64 * 325;         // 320*65
    float* invl = Vs + 320 * 65;         // 64

    const int tid = threadIdx.x;
    const int q0 = blockIdx.x * 64;
    const int h = blockIdx.y;
    const int b = blockIdx.z;
    const int xl = XLEN[b];
    const size_t base = ((size_t)b * S_) * DM_ + h * D_;

    // ---- stage Q tile (transposed, d-major) ----
    {
        const int i = tid >> 2;
        const int dg = tid & 3;
        const float* qrow = Q + base + (size_t)(q0 + i) * DM_;
#pragma unroll
        for (int t = 0; t < 4; t++) {
            const int d4 = 4 * (dg + 4 * t);
            float4 qv = *(const float4*)(qrow + d4);
            Qs[(d4 + 0) * 65 + i] = qv.x;
            Qs[(d4 + 1) * 65 + i] = qv.y;
            Qs[(d4 + 2) * 65 + i] = qv.z;
            Qs[(d4 + 3) * 65 + i] = qv.w;
        }
    }

    const int tx = tid & 15;   // -> 4 queries
    const int ty = tid >> 4;   // -> 4 keys (energy) / 4 dims (AV)
    const int kbase0 = q0 - 128;

    // ---- energies over 5 key chunks of 64 ----
    for (int c = 0; c < 5; c++) {
        const int kb = kbase0 + c * 64;
        __syncthreads();   // prev chunk's energy reads done; Qs visible on c==0
        {
            const int j = tid >> 2;
            const int dg = tid & 3;
            const int jabs = kb + j;
            const bool inr = (jabs >= 0) && (jabs < S_);
            const float* krow = K + base + (size_t)jabs * DM_;
            const float* vrow = V + base + (size_t)jabs * DM_;
#pragma unroll
            for (int t = 0; t < 4; t++) {
                const int d4 = 4 * (dg + 4 * t);
                float* vdst = Vs + (size_t)(c * 64 + j) * 65 + d4;
                if (inr) {
                    float4 kv = *(const float4*)(krow + d4);
                    Ks[(d4 + 0) * 65 + j] = kv.x;
                    Ks[(d4 + 1) * 65 + j] = kv.y;
                    Ks[(d4 + 2) * 65 + j] = kv.z;
                    Ks[(d4 + 3) * 65 + j] = kv.w;
                    float4 vv = *(const float4*)(vrow + d4);
                    vdst[0] = vv.x; vdst[1] = vv.y; vdst[2] = vv.z; vdst[3] = vv.w;
                } else {
                    vdst[0] = 0.f; vdst[1] = 0.f; vdst[2] = 0.f; vdst[3] = 0.f;
                }
            }
        }
        __syncthreads();

        float acc[4][4];
#pragma unroll
        for (int r = 0; r < 4; r++)
#pragma unroll
            for (int cc = 0; cc < 4; cc++) acc[r][cc] = 0.f;

        const float* qp = Qs + 4 * tx;
        const float* kp = Ks + 4 * ty;
#pragma unroll 8
        for (int d = 0; d < 64; d++) {
            const float qa = qp[d * 65 + 0], qb = qp[d * 65 + 1];
            const float qc = qp[d * 65 + 2], qd = qp[d * 65 + 3];
            const float ka = kp[d * 65 + 0], kb2 = kp[d * 65 + 1];
            const float kc = kp[d * 65 + 2], kd = kp[d * 65 + 3];
            acc[0][0] += qa * ka; acc[0][1] += qa * kb2; acc[0][2] += qa * kc; acc[0][3] += qa * kd;
            acc[1][0] += qb * ka; acc[1][1] += qb * kb2; acc[1][2] += qb * kc; acc[1][3] += qb * kd;
            acc[2][0] += qc * ka; acc[2][1] += qc * kb2; acc[2][2] += qc * kc; acc[2][3] += qc * kd;
            acc[3][0] += qd * ka; acc[3][1] += qd * kb2; acc[3][2] += qd * kc; acc[3][3] += qd * kd;
        }
#pragma unroll
        for (int r = 0; r < 4; r++) {
            const int iabs = q0 + 4 * tx + r;
#pragma unroll
            for (int cc = 0; cc < 4; cc++) {
                const int jabs = kb + 4 * ty + cc;
                const bool valid = (jabs >= 0) && (jabs < S_) && (jabs < xl) &&
                                   (jabs - iabs <= 128) && (iabs - jabs <= 128);
                Ss[(4 * tx + r) * 325 + (c * 64 + 4 * ty + cc)] =
                    valid ? acc[r][cc] * 0.125f : -1e30f;
            }
        }
    }
    __syncthreads();

    // ---- row softmax over 320 keys (warp per 8 rows) ----
    {
        const int w = tid >> 5, lane = tid & 31;
        for (int rr = 0; rr < 8; rr++) {
            const int i = w * 8 + rr;
            float* row = Ss + i * 325;
            float vals[10];
            float m = -3.0e38f;
#pragma unroll
            for (int t = 0; t < 10; t++) {
                vals[t] = row[lane + 32 * t];
                m = fmaxf(m, vals[t]);
            }
#pragma unroll
            for (int o = 16; o; o >>= 1) m = fmaxf(m, __shfl_xor_sync(0xffffffffu, m, o));
            float l = 0.f;
#pragma unroll
            for (int t = 0; t < 10; t++) {
                const float p = __expf(vals[t] - m);
                row[lane + 32 * t] = p;
                l += p;
            }
#pragma unroll
            for (int o = 16; o; o >>= 1) l += __shfl_xor_sync(0xffffffffu, l, o);
            if (lane == 0) invl[i] = 1.0f / l;
        }
    }
    __syncthreads();

    // ---- AV: ctx[i][d] = sum_j P[i][j] * V[j][d] ----
    {
        float acc[4][4];
#pragma unroll
        for (int r = 0; r < 4; r++)
#pragma unroll
            for (int cc = 0; cc < 4; cc++) acc[r][cc] = 0.f;

        const float* pp = Ss + (4 * tx) * 325;
        const float* vp = Vs + 4 * ty;
#pragma unroll 4
        for (int jj = 0; jj < 320; jj++) {
            const float p0 = pp[jj];
            const float p1 = pp[325 + jj];
            const float p2 = pp[650 + jj];
            const float p3 = pp[975 + jj];
            const float v0 = vp[jj * 65 + 0], v1 = vp[jj * 65 + 1];
            const float v2 = vp[jj * 65 + 2], v3 = vp[jj * 65 + 3];
            acc[0][0] += p0 * v0; acc[0][1] += p0 * v1; acc[0][2] += p0 * v2; acc[0][3] += p0 * v3;
            acc[1][0] += p1 * v0; acc[1][1] += p1 * v1; acc[1][2] += p1 * v2; acc[1][3] += p1 * v3;
            acc[2][0] += p2 * v0; acc[2][1] += p2 * v1; acc[2][2] += p2 * v2; acc[2][3] += p2 * v3;
            acc[3][0] += p3 * v0; acc[3][1] += p3 * v1; acc[3][2] += p3 * v2; acc[3][3] += p3 * v3;
        }

#pragma unroll
        for (int r = 0; r < 4; r++) {
            const int i = 4 * tx + r;
            const int iabs = q0 + i;
            int lo = iabs - 128;
            if (lo < 0) lo = 0;
            const bool deg = (lo >= xl);  // no valid key in band -> uniform over all S keys
            const float il = invl[i];
            float* crow = CTX + base + (size_t)iabs * DM_ + 4 * ty;
            const float* vm = VMEAN + b * DM_ + h * D_ + 4 * ty;
            float4 o;
            o.x = deg ? vm[0] : acc[r][0] * il;
            o.y = deg ? vm[1] : acc[r][1] * il;
            o.z = deg ? vm[2] : acc[r][2] * il;
            o.w = deg ? vm[3] : acc[r][3] * il;
            *(float4*)crow = o;
        }
    }
}

// ---------------- launch ----------------
extern "C" void kernel_launch(void* const* d_in, const int* in_sizes, int n_in,
                              void* d_out, int out_size) {
    const float* x  = (const float*)d_in[0];
    const float* Wq = (const float*)d_in[1];
    const float* bq = (const float*)d_in[2];
    const float* Wk = (const float*)d_in[3];
    const float* bk = (const float*)d_in[4];
    const float* Wv = (const float*)d_in[5];
    const float* bv = (const float*)d_in[6];
    const float* Wo = (const float*)d_in[7];
    const float* bo = (const float*)d_in[8];
    const int* xlen = (const int*)d_in[9];
    float* out = (float*)d_out;

    float *q, *k, *v, *ctx, *part, *vmean;
    cudaGetSymbolAddress((void**)&q, g_q);
    cudaGetSymbolAddress((void**)&k, g_k);
    cudaGetSymbolAddress((void**)&v, g_v);
    cudaGetSymbolAddress((void**)&ctx, g_ctx);
    cudaGetSymbolAddress((void**)&part, g_part);
    cudaGetSymbolAddress((void**)&vmean, g_vmean);

    cudaFuncSetAttribute(attn_kernel, cudaFuncAttributeMaxDynamicSharedMemorySize,
                         ATT_SMEM_BYTES);

    dim3 gg(B_ * S_ / 128, DM_ / 128);
    sgemm_bias<<<gg, 256>>>(x, Wq, bq, q);
    sgemm_bias<<<gg, 256>>>(x, Wk, bk, k);
    sgemm_bias<<<gg, 256>>>(x, Wv, bv, v);

    vmean_partial<<<dim3(16, B_), DM_>>>(v, part);
    vmean_final<<<B_, DM_>>>(part, vmean);

    attn_kernel<<<dim3(S_ / 64, H_, B_), 256, ATT_SMEM_BYTES>>>(q, k, v, vmean, xlen, ctx);

    sgemm_bias<<<gg, 256>>>(ctx, Wo, bo, out);
}

// round 3
// speedup vs baseline: 1.1102x; 1.1102x over previous
#include <cuda_runtime.h>
#include <cuda_bf16.h>
#include <cstdint>

#define B_  4
#define S_  2048
#define DM_ 512
#define H_  8
#define D_  64
#define K3_ 1536            // 3x hi/lo expanded K
#define NCHUNK 24           // K3_/64

// ================= helpers =================
__device__ __forceinline__ uint32_t smem_u32(const void* p) {
    uint32_t a;
    asm("{ .reg .u64 t; cvta.to.shared.u64 t, %1; cvt.u32.u64 %0, t; }" : "=r"(a) : "l"(p));
    return a;
}
#define SWZ128(off) ((off) ^ (((off) >> 3) & 0x70))

__device__ __forceinline__ void cp_async16(uint32_t dst, const void* src) {
    asm volatile("cp.async.cg.shared.global [%0], [%1], 16;" :: "r"(dst), "l"(src));
}
#define CP_COMMIT() asm volatile("cp.async.commit_group;" ::: "memory")
#define CP_WAIT(n)  asm volatile("cp.async.wait_group %0;" :: "n"(n) : "memory")

__device__ __forceinline__ void ldmx4(uint32_t& r0, uint32_t& r1, uint32_t& r2, uint32_t& r3,
                                      uint32_t addr) {
    asm volatile("ldmatrix.sync.aligned.m8n8.x4.shared.b16 {%0,%1,%2,%3}, [%4];"
                 : "=r"(r0), "=r"(r1), "=r"(r2), "=r"(r3) : "r"(addr));
}
__device__ __forceinline__ void mma16816(float* c, const uint32_t* a, uint32_t b0, uint32_t b1) {
    asm volatile(
        "mma.sync.aligned.m16n8k16.row.col.f32.bf16.bf16.f32 "
        "{%0,%1,%2,%3}, {%4,%5,%6,%7}, {%8,%9}, {%0,%1,%2,%3};"
        : "+f"(c[0]), "+f"(c[1]), "+f"(c[2]), "+f"(c[3])
        : "r"(a[0]), "r"(a[1]), "r"(a[2]), "r"(a[3]), "r"(b0), "r"(b1));
}

// ================= scratch =================
__device__ float g_q[B_ * S_ * DM_];
__device__ float g_k[B_ * S_ * DM_];
__device__ float g_v[B_ * S_ * DM_];
__device__ float g_ctx[B_ * S_ * DM_];
__device__ float g_part[B_ * 64 * DM_];
__device__ float g_vmean[B_ * DM_];
__device__ __nv_bfloat16 g_x3[B_ * S_ * K3_];     // [8192, 1536] (hi,lo,hi)
__device__ __nv_bfloat16 g_w3t[DM_ * K3_];        // [N=512, 1536] (hi,hi,lo)

// ================= split kernels =================
// X [8192,512] f32 -> X3 [8192,1536] bf16 (hi,lo,hi per k)
__global__ __launch_bounds__(256) void split_act3(const float* __restrict__ X,
                                                  __nv_bfloat16* __restrict__ X3) {
    const int idx = blockIdx.x * 256 + threadIdx.x;   // 8192*64 groups of 8 k
    const int m = idx >> 6, g = idx & 63;
    const float4 f0 = *(const float4*)(X + (size_t)m * 512 + g * 8);
    const float4 f1 = *(const float4*)(X + (size_t)m * 512 + g * 8 + 4);
    float v[8] = {f0.x, f0.y, f0.z, f0.w, f1.x, f1.y, f1.z, f1.w};
    __nv_bfloat16 o[24];
#pragma unroll
    for (int i = 0; i < 8; i++) {
        const __nv_bfloat16 hi = __float2bfloat16(v[i]);
        const __nv_bfloat16 lo = __float2bfloat16(v[i] - __bfloat162float(hi));
        o[3 * i] = hi; o[3 * i + 1] = lo; o[3 * i + 2] = hi;
    }
    uint4* dst = (uint4*)(X3 + (size_t)m * K3_ + g * 24);
    dst[0] = ((uint4*)o)[0];
    dst[1] = ((uint4*)o)[1];
    dst[2] = ((uint4*)o)[2];
}

// W [K=512, N=512] f32 -> W3t [N=512, 1536] bf16 (hi,hi,lo per k), transposed via smem
__global__ __launch_bounds__(1024) void split_w3(const float* __restrict__ W,
                                                 __nv_bfloat16* __restrict__ W3t) {
    __shared__ float t[32][33];
    const int k0 = blockIdx.y * 32, n0 = blockIdx.x * 32;
    const int tx = threadIdx.x, ty = threadIdx.y;
    t[ty][tx] = W[(size_t)(k0 + ty) * 512 + n0 + tx];
    __syncthreads();
    const float v = t[tx][ty];           // W[k0+tx][n0+ty]
    const __nv_bfloat16 hi = __float2bfloat16(v);
    const __nv_bfloat16 lo = __float2bfloat16(v - __bfloat162float(hi));
    __nv_bfloat16* dst = W3t + (size_t)(n0 + ty) * K3_ + 3 * (k0 + tx);
    dst[0] = hi; dst[1] = hi; dst[2] = lo;
}

// ================= HMMA GEMM: C[8192,512] = A3 @ W3t^T + bias =================
// CTA 128x128, BK=64 bf16 (128B rows, SW128), 3-stage cp.async ring, 8 warps (2m x 4n).
#define GEMM_SMEM (3 * 32768 + 1024)

__global__ __launch_bounds__(256, 2) void gemm_mma(const __nv_bfloat16* __restrict__ A3,
                                                   const __nv_bfloat16* __restrict__ B3,
                                                   const float* __restrict__ bias,
                                                   float* __restrict__ C) {
    extern __shared__ char smraw[];
    const uint32_t sbase = (smem_u32(smraw) + 1023) & ~1023u;
    const int tid = threadIdx.x;
    const int wid = tid >> 5, lane = tid & 31;
    const int bm = blockIdx.x * 128, bn = blockIdx.y * 128;
    const int wm0 = (wid & 1) * 64, wn0 = (wid >> 1) * 32;

    // per-thread load mapping (8 x 16B per chunk: A tile 128x64, B tile 128x64)
    const int l_isB = tid >> 7;                 // threads 0-127: A, 128-255: B
    const int l_row = (tid & 127);              // row 0..127
    // each thread loads its row's 8 segments? No: 2048 segs / 256 thr = 8 -> one row, 8 segs.
    const __nv_bfloat16* l_src = (l_isB ? B3 + (size_t)(bn + l_row) * K3_
                                        : A3 + (size_t)(bm + l_row) * K3_);
    const uint32_t l_dst = sbase /*+buf*/ + (l_isB ? 16384 : 0);

    float acc[4][4][4];
#pragma unroll
    for (int a = 0; a < 4; a++)
#pragma unroll
        for (int b = 0; b < 4; b++)
#pragma unroll
            for (int c = 0; c < 4; c++) acc[a][b][c] = 0.f;

    // ---- preload chunks 0,1,2 ----
#pragma unroll
    for (int c = 0; c < 3; c++) {
        const uint32_t db = l_dst + c * 32768;
        const __nv_bfloat16* sp = l_src + c * 64;
#pragma unroll
        for (int seg = 0; seg < 8; seg++)
            cp_async16(db + SWZ128(l_row * 128 + seg * 16), sp + seg * 8);
        CP_COMMIT();
    }

    for (int c = 0; c < NCHUNK; c++) {
        CP_WAIT(2);
        __syncthreads();
        const uint32_t abuf = sbase + (c % 3) * 32768;
        const uint32_t bbuf = abuf + 16384;
#pragma unroll
        for (int ks = 0; ks < 4; ks++) {
            const int cb = ks * 32 + ((lane >> 4) * 16);
            uint32_t bf[2][4];
#pragma unroll
            for (int nh = 0; nh < 2; nh++) {
                const int r = wn0 + nh * 16 + (lane & 15);
                ldmx4(bf[nh][0], bf[nh][1], bf[nh][2], bf[nh][3],
                      bbuf + SWZ128(r * 128 + cb));
            }
#pragma unroll
            for (int mf = 0; mf < 4; mf++) {
                uint32_t a[4];
                const int r = wm0 + mf * 16 + (lane & 15);
                ldmx4(a[0], a[1], a[2], a[3], abuf + SWZ128(r * 128 + cb));
#pragma unroll
                for (int nf = 0; nf < 4; nf++) {
                    const uint32_t b0 = bf[nf >> 1][(nf & 1)];      // r0 or r1
                    const uint32_t b1 = bf[nf >> 1][(nf & 1) + 2];  // r2 or r3
                    mma16816(acc[mf][nf], a, b0, b1);
                }
            }
        }
        __syncthreads();
        if (c + 3 < NCHUNK) {
            const uint32_t db = l_dst + ((c + 3) % 3) * 32768;
            const __nv_bfloat16* sp = l_src + (c + 3) * 64;
#pragma unroll
            for (int seg = 0; seg < 8; seg++)
                cp_async16(db + SWZ128(l_row * 128 + seg * 16), sp + seg * 8);
        }
        CP_COMMIT();   // always commit (possibly empty) to keep wait_group invariant
    }

    // ---- epilogue: direct gmem + bias ----
    const int qr = lane >> 2, qc = (lane & 3) * 2;
#pragma unroll
    for (int mf = 0; mf < 4; mf++) {
        const int row = bm + wm0 + mf * 16 + qr;
#pragma unroll
        for (int nf = 0; nf < 4; nf++) {
            const int col = bn + wn0 + nf * 8 + qc;
            const float b0 = bias[col], b1 = bias[col + 1];
            float2 lo, hi;
            lo.x = acc[mf][nf][0] + b0; lo.y = acc[mf][nf][1] + b1;
            hi.x = acc[mf][nf][2] + b0; hi.y = acc[mf][nf][3] + b1;
            *(float2*)(C + (size_t)row * 512 + col) = lo;
            *(float2*)(C + (size_t)(row + 8) * 512 + col) = hi;
        }
    }
}

// ================= V mean =================
__global__ void vmean_partial(const float* __restrict__ V, float* __restrict__ part) {
    const int b = blockIdx.y, sc = blockIdx.x, c = threadIdx.x;
    const float* p = V + ((size_t)b * S_ + sc * 32) * DM_ + c;
    float s = 0.f;
#pragma unroll 8
    for (int t = 0; t < 32; t++) s += p[(size_t)t * DM_];
    part[((size_t)b * 64 + sc) * DM_ + c] = s;
}

__global__ void vmean_final(const float* __restrict__ part, float* __restrict__ vm) {
    const int b = blockIdx.x, c = threadIdx.x;
    const float* p = part + (size_t)b * 64 * DM_ + c;
    float s = 0.f;
#pragma unroll
    for (int t = 0; t < 64; t++) s += p[(size_t)t * DM_];
    vm[b * DM_ + c] = s * (1.0f / 2048.0f);
}

// ================= banded attention (fp32) =================
#define ATT_SMEM_FLOATS (64 * 65 + 64 * 65 + 64 * 325 + 320 * 65 + 64)
#define ATT_SMEM_BYTES  (ATT_SMEM_FLOATS * 4)

__global__ __launch_bounds__(256, 1) void attn_kernel(const float* __restrict__ Q,
                                                      const float* __restrict__ K,
                                                      const float* __restrict__ V,
                                                      const float* __restrict__ VMEAN,
                                                      const int* __restrict__ XLEN,
                                                      float* __restrict__ CTX) {
    extern __shared__ float sm[];
    float* Qs   = sm;
    float* Ks   = Qs + 64 * 65;
    float* Ss   = Ks + 64 * 65;
    float* Vs   = Ss + 64 * 325;
    float* invl = Vs + 320 * 65;

    const int tid = threadIdx.x;
    const int q0 = blockIdx.x * 64;
    const int h = blockIdx.y;
    const int b = blockIdx.z;
    const int xl = XLEN[b];
    const size_t base = ((size_t)b * S_) * DM_ + h * D_;

    {
        const int i = tid >> 2;
        const int dg = tid & 3;
        const float* qrow = Q + base + (size_t)(q0 + i) * DM_;
#pragma unroll
        for (int t = 0; t < 4; t++) {
            const int d4 = 4 * (dg + 4 * t);
            float4 qv = *(const float4*)(qrow + d4);
            Qs[(d4 + 0) * 65 + i] = qv.x;
            Qs[(d4 + 1) * 65 + i] = qv.y;
            Qs[(d4 + 2) * 65 + i] = qv.z;
            Qs[(d4 + 3) * 65 + i] = qv.w;
        }
    }

    const int tx = tid & 15;
    const int ty = tid >> 4;
    const int kbase0 = q0 - 128;

    for (int c = 0; c < 5; c++) {
        const int kb = kbase0 + c * 64;
        __syncthreads();
        {
            const int j = tid >> 2;
            const int dg = tid & 3;
            const int jabs = kb + j;
            const bool inr = (jabs >= 0) && (jabs < S_);
            const float* krow = K + base + (size_t)jabs * DM_;
            const float* vrow = V + base + (size_t)jabs * DM_;
#pragma unroll
            for (int t = 0; t < 4; t++) {
                const int d4 = 4 * (dg + 4 * t);
                float* vdst = Vs + (size_t)(c * 64 + j) * 65 + d4;
                if (inr) {
                    float4 kv = *(const float4*)(krow + d4);
                    Ks[(d4 + 0) * 65 + j] = kv.x;
                    Ks[(d4 + 1) * 65 + j] = kv.y;
                    Ks[(d4 + 2) * 65 + j] = kv.z;
                    Ks[(d4 + 3) * 65 + j] = kv.w;
                    float4 vv = *(const float4*)(vrow + d4);
                    vdst[0] = vv.x; vdst[1] = vv.y; vdst[2] = vv.z; vdst[3] = vv.w;
                } else {
                    vdst[0] = 0.f; vdst[1] = 0.f; vdst[2] = 0.f; vdst[3] = 0.f;
                }
            }
        }
        __syncthreads();

        float acc[4][4];
#pragma unroll
        for (int r = 0; r < 4; r++)
#pragma unroll
            for (int cc = 0; cc < 4; cc++) acc[r][cc] = 0.f;

        const float* qp = Qs + 4 * tx;
        const float* kp = Ks + 4 * ty;
#pragma unroll 8
        for (int d = 0; d < 64; d++) {
            const float qa = qp[d * 65 + 0], qb = qp[d * 65 + 1];
            const float qc = qp[d * 65 + 2], qd = qp[d * 65 + 3];
            const float ka = kp[d * 65 + 0], kb2 = kp[d * 65 + 1];
            const float kc = kp[d * 65 + 2], kd = kp[d * 65 + 3];
            acc[0][0] += qa * ka; acc[0][1] += qa * kb2; acc[0][2] += qa * kc; acc[0][3] += qa * kd;
            acc[1][0] += qb * ka; acc[1][1] += qb * kb2; acc[1][2] += qb * kc; acc[1][3] += qb * kd;
            acc[2][0] += qc * ka; acc[2][1] += qc * kb2; acc[2][2] += qc * kc; acc[2][3] += qc * kd;
            acc[3][0] += qd * ka; acc[3][1] += qd * kb2; acc[3][2] += qd * kc; acc[3][3] += qd * kd;
        }
#pragma unroll
        for (int r = 0; r < 4; r++) {
            const int iabs = q0 + 4 * tx + r;
#pragma unroll
            for (int cc = 0; cc < 4; cc++) {
                const int jabs = kb + 4 * ty + cc;
                const bool valid = (jabs >= 0) && (jabs < S_) && (jabs < xl) &&
                                   (jabs - iabs <= 128) && (iabs - jabs <= 128);
                Ss[(4 * tx + r) * 325 + (c * 64 + 4 * ty + cc)] =
                    valid ? acc[r][cc] * 0.125f : -1e30f;
            }
        }
    }
    __syncthreads();

    {
        const int w = tid >> 5, lane = tid & 31;
        for (int rr = 0; rr < 8; rr++) {
            const int i = w * 8 + rr;
            float* row = Ss + i * 325;
            float vals[10];
            float m = -3.0e38f;
#pragma unroll
            for (int t = 0; t < 10; t++) {
                vals[t] = row[lane + 32 * t];
                m = fmaxf(m, vals[t]);
            }
#pragma unroll
            for (int o = 16; o; o >>= 1) m = fmaxf(m, __shfl_xor_sync(0xffffffffu, m, o));
            float l = 0.f;
#pragma unroll
            for (int t = 0; t < 10; t++) {
                const float p = __expf(vals[t] - m);
                row[lane + 32 * t] = p;
                l += p;
            }
#pragma unroll
            for (int o = 16; o; o >>= 1) l += __shfl_xor_sync(0xffffffffu, l, o);
            if (lane == 0) invl[i] = 1.0f / l;
        }
    }
    __syncthreads();

    {
        float acc[4][4];
#pragma unroll
        for (int r = 0; r < 4; r++)
#pragma unroll
            for (int cc = 0; cc < 4; cc++) acc[r][cc] = 0.f;

        const float* pp = Ss + (4 * tx) * 325;
        const float* vp = Vs + 4 * ty;
#pragma unroll 4
        for (int jj = 0; jj < 320; jj++) {
            const float p0 = pp[jj];
            const float p1 = pp[325 + jj];
            const float p2 = pp[650 + jj];
            const float p3 = pp[975 + jj];
            const float v0 = vp[jj * 65 + 0], v1 = vp[jj * 65 + 1];
            const float v2 = vp[jj * 65 + 2], v3 = vp[jj * 65 + 3];
            acc[0][0] += p0 * v0; acc[0][1] += p0 * v1; acc[0][2] += p0 * v2; acc[0][3] += p0 * v3;
            acc[1][0] += p1 * v0; acc[1][1] += p1 * v1; acc[1][2] += p1 * v2; acc[1][3] += p1 * v3;
            acc[2][0] += p2 * v0; acc[2][1] += p2 * v1; acc[2][2] += p2 * v2; acc[2][3] += p2 * v3;
            acc[3][0] += p3 * v0; acc[3][1] += p3 * v1; acc[3][2] += p3 * v2; acc[3][3] += p3 * v3;
        }

#pragma unroll
        for (int r = 0; r < 4; r++) {
            const int i = 4 * tx + r;
            const int iabs = q0 + i;
            int lo = iabs - 128;
            if (lo < 0) lo = 0;
            const bool deg = (lo >= xl);
            const float il = invl[i];
            float* crow = CTX + base + (size_t)iabs * DM_ + 4 * ty;
            const float* vm = VMEAN + b * DM_ + h * D_ + 4 * ty;
            float4 o;
            o.x = deg ? vm[0] : acc[r][0] * il;
            o.y = deg ? vm[1] : acc[r][1] * il;
            o.z = deg ? vm[2] : acc[r][2] * il;
            o.w = deg ? vm[3] : acc[r][3] * il;
            *(float4*)crow = o;
        }
    }
}

// ================= launch =================
extern "C" void kernel_launch(void* const* d_in, const int* in_sizes, int n_in,
                              void* d_out, int out_size) {
    const float* x  = (const float*)d_in[0];
    const float* Wq = (const float*)d_in[1];
    const float* bq = (const float*)d_in[2];
    const float* Wk = (const float*)d_in[3];
    const float* bk = (const float*)d_in[4];
    const float* Wv = (const float*)d_in[5];
    const float* bv = (const float*)d_in[6];
    const float* Wo = (const float*)d_in[7];
    const float* bo = (const float*)d_in[8];
    const int* xlen = (const int*)d_in[9];
    float* out = (float*)d_out;

    float *q, *k, *v, *ctx, *part, *vmean;
    __nv_bfloat16 *x3, *w3t;
    cudaGetSymbolAddress((void**)&q, g_q);
    cudaGetSymbolAddress((void**)&k, g_k);
    cudaGetSymbolAddress((void**)&v, g_v);
    cudaGetSymbolAddress((void**)&ctx, g_ctx);
    cudaGetSymbolAddress((void**)&part, g_part);
    cudaGetSymbolAddress((void**)&vmean, g_vmean);
    cudaGetSymbolAddress((void**)&x3, g_x3);
    cudaGetSymbolAddress((void**)&w3t, g_w3t);

    cudaFuncSetAttribute(attn_kernel, cudaFuncAttributeMaxDynamicSharedMemorySize,
                         ATT_SMEM_BYTES);
    cudaFuncSetAttribute(gemm_mma, cudaFuncAttributeMaxDynamicSharedMemorySize,
                         GEMM_SMEM);

    const dim3 gemm_grid(B_ * S_ / 128, DM_ / 128);
    const dim3 wgrid(16, 16), wblk(32, 32);

    split_act3<<<B_ * S_ * 64 / 256, 256>>>(x, x3);
    split_w3<<<wgrid, wblk>>>(Wq, w3t);
    gemm_mma<<<gemm_grid, 256, GEMM_SMEM>>>(x3, w3t, bq, q);
    split_w3<<<wgrid, wblk>>>(Wk, w3t);
    gemm_mma<<<gemm_grid, 256, GEMM_SMEM>>>(x3, w3t, bk, k);
    split_w3<<<wgrid, wblk>>>(Wv, w3t);
    gemm_mma<<<gemm_grid, 256, GEMM_SMEM>>>(x3, w3t, bv, v);

    vmean_partial<<<dim3(64, B_), DM_>>>(v, part);
    vmean_final<<<B_, DM_>>>(part, vmean);

    attn_kernel<<<dim3(S_ / 64, H_, B_), 256, ATT_SMEM_BYTES>>>(q, k, v, vmean, xlen, ctx);

    split_act3<<<B_ * S_ * 64 / 256, 256>>>(ctx, x3);
    split_w3<<<wgrid, wblk>>>(Wo, w3t);
    gemm_mma<<<gemm_grid, 256, GEMM_SMEM>>>(x3, w3t, bo, out);
}

// round 4
// speedup vs baseline: 1.2174x; 1.0965x over previous
#include <cuda_runtime.h>
#include <cuda_bf16.h>
#include <cstdint>

#define B_  4
#define S_  2048
#define DM_ 512
#define H_  8
#define D_  64
#define K3_ 1536            // 3x hi/lo expanded K for projections
#define NCHUNK 24           // K3_/64

// ================= helpers =================
__device__ __forceinline__ uint32_t smem_u32(const void* p) {
    uint32_t a;
    asm("{ .reg .u64 t; cvta.to.shared.u64 t, %1; cvt.u32.u64 %0, t; }" : "=r"(a) : "l"(p));
    return a;
}
#define SWZ128(off) ((off) ^ (((off) >> 3) & 0x70))

__device__ __forceinline__ void cp_async16(uint32_t dst, const void* src) {
    asm volatile("cp.async.cg.shared.global [%0], [%1], 16;" :: "r"(dst), "l"(src));
}
#define CP_COMMIT() asm volatile("cp.async.commit_group;" ::: "memory")
#define CP_WAIT(n)  asm volatile("cp.async.wait_group %0;" :: "n"(n) : "memory")

__device__ __forceinline__ void ldmx4(uint32_t& r0, uint32_t& r1, uint32_t& r2, uint32_t& r3,
                                      uint32_t addr) {
    asm volatile("ldmatrix.sync.aligned.m8n8.x4.shared.b16 {%0,%1,%2,%3}, [%4];"
                 : "=r"(r0), "=r"(r1), "=r"(r2), "=r"(r3) : "r"(addr));
}
__device__ __forceinline__ void mma16816(float* c, const uint32_t* a, uint32_t b0, uint32_t b1) {
    asm volatile(
        "mma.sync.aligned.m16n8k16.row.col.f32.bf16.bf16.f32 "
        "{%0,%1,%2,%3}, {%4,%5,%6,%7}, {%8,%9}, {%0,%1,%2,%3};"
        : "+f"(c[0]), "+f"(c[1]), "+f"(c[2]), "+f"(c[3])
        : "r"(a[0]), "r"(a[1]), "r"(a[2]), "r"(a[3]), "r"(b0), "r"(b1));
}
__device__ __forceinline__ void split2(float f, __nv_bfloat16& hi, __nv_bfloat16& lo) {
    hi = __float2bfloat16(f);
    lo = __float2bfloat16(f - __bfloat162float(hi));
}

// ================= scratch =================
__device__ float g_q[B_ * S_ * DM_];
__device__ float g_k[B_ * S_ * DM_];
__device__ float g_v[B_ * S_ * DM_];
__device__ float g_ctx[B_ * S_ * DM_];
__device__ float g_part[B_ * 64 * DM_];
__device__ float g_vmean[B_ * DM_];
__device__ __nv_bfloat16 g_x3[B_ * S_ * K3_];     // [8192, 1536] (hi,lo,hi)
__device__ __nv_bfloat16 g_w3t[DM_ * K3_];        // [N=512, 1536] (hi,hi,lo)

// ================= split kernels =================
__global__ __launch_bounds__(256) void split_act3(const float* __restrict__ X,
                                                  __nv_bfloat16* __restrict__ X3) {
    const int idx = blockIdx.x * 256 + threadIdx.x;
    const int m = idx >> 6, g = idx & 63;
    const float4 f0 = *(const float4*)(X + (size_t)m * 512 + g * 8);
    const float4 f1 = *(const float4*)(X + (size_t)m * 512 + g * 8 + 4);
    float v[8] = {f0.x, f0.y, f0.z, f0.w, f1.x, f1.y, f1.z, f1.w};
    __nv_bfloat16 o[24];
#pragma unroll
    for (int i = 0; i < 8; i++) {
        __nv_bfloat16 hi, lo; split2(v[i], hi, lo);
        o[3 * i] = hi; o[3 * i + 1] = lo; o[3 * i + 2] = hi;
    }
    uint4* dst = (uint4*)(X3 + (size_t)m * K3_ + g * 24);
    dst[0] = ((uint4*)o)[0];
    dst[1] = ((uint4*)o)[1];
    dst[2] = ((uint4*)o)[2];
}

__global__ __launch_bounds__(1024) void split_w3(const float* __restrict__ W,
                                                 __nv_bfloat16* __restrict__ W3t) {
    __shared__ float t[32][33];
    const int k0 = blockIdx.y * 32, n0 = blockIdx.x * 32;
    const int tx = threadIdx.x, ty = threadIdx.y;
    t[ty][tx] = W[(size_t)(k0 + ty) * 512 + n0 + tx];
    __syncthreads();
    const float v = t[tx][ty];
    __nv_bfloat16 hi, lo; split2(v, hi, lo);
    __nv_bfloat16* dst = W3t + (size_t)(n0 + ty) * K3_ + 3 * (k0 + tx);
    dst[0] = hi; dst[1] = hi; dst[2] = lo;
}

// ================= HMMA GEMM (unchanged from R3, proven) =================
#define GEMM_SMEM (3 * 32768 + 1024)

__global__ __launch_bounds__(256, 2) void gemm_mma(const __nv_bfloat16* __restrict__ A3,
                                                   const __nv_bfloat16* __restrict__ B3,
                                                   const float* __restrict__ bias,
                                                   float* __restrict__ C) {
    extern __shared__ char smraw[];
    const uint32_t sbase = (smem_u32(smraw) + 1023) & ~1023u;
    const int tid = threadIdx.x;
    const int wid = tid >> 5, lane = tid & 31;
    const int bm = blockIdx.x * 128, bn = blockIdx.y * 128;
    const int wm0 = (wid & 1) * 64, wn0 = (wid >> 1) * 32;

    const int l_isB = tid >> 7;
    const int l_row = (tid & 127);
    const __nv_bfloat16* l_src = (l_isB ? B3 + (size_t)(bn + l_row) * K3_
                                        : A3 + (size_t)(bm + l_row) * K3_);
    const uint32_t l_dst = sbase + (l_isB ? 16384 : 0);

    float acc[4][4][4];
#pragma unroll
    for (int a = 0; a < 4; a++)
#pragma unroll
        for (int b = 0; b < 4; b++)
#pragma unroll
            for (int c = 0; c < 4; c++) acc[a][b][c] = 0.f;

#pragma unroll
    for (int c = 0; c < 3; c++) {
        const uint32_t db = l_dst + c * 32768;
        const __nv_bfloat16* sp = l_src + c * 64;
#pragma unroll
        for (int seg = 0; seg < 8; seg++)
            cp_async16(db + SWZ128(l_row * 128 + seg * 16), sp + seg * 8);
        CP_COMMIT();
    }

    for (int c = 0; c < NCHUNK; c++) {
        CP_WAIT(2);
        __syncthreads();
        const uint32_t abuf = sbase + (c % 3) * 32768;
        const uint32_t bbuf = abuf + 16384;
#pragma unroll
        for (int ks = 0; ks < 4; ks++) {
            const int cb = ks * 32 + ((lane >> 4) * 16);
            uint32_t bf[2][4];
#pragma unroll
            for (int nh = 0; nh < 2; nh++) {
                const int r = wn0 + nh * 16 + (lane & 15);
                ldmx4(bf[nh][0], bf[nh][1], bf[nh][2], bf[nh][3],
                      bbuf + SWZ128(r * 128 + cb));
            }
#pragma unroll
            for (int mf = 0; mf < 4; mf++) {
                uint32_t a[4];
                const int r = wm0 + mf * 16 + (lane & 15);
                ldmx4(a[0], a[1], a[2], a[3], abuf + SWZ128(r * 128 + cb));
#pragma unroll
                for (int nf = 0; nf < 4; nf++) {
                    const uint32_t b0 = bf[nf >> 1][(nf & 1)];
                    const uint32_t b1 = bf[nf >> 1][(nf & 1) + 2];
                    mma16816(acc[mf][nf], a, b0, b1);
                }
            }
        }
        __syncthreads();
        if (c + 3 < NCHUNK) {
            const uint32_t db = l_dst + ((c + 3) % 3) * 32768;
            const __nv_bfloat16* sp = l_src + (c + 3) * 64;
#pragma unroll
            for (int seg = 0; seg < 8; seg++)
                cp_async16(db + SWZ128(l_row * 128 + seg * 16), sp + seg * 8);
        }
        CP_COMMIT();
    }

    const int qr = lane >> 2, qc = (lane & 3) * 2;
#pragma unroll
    for (int mf = 0; mf < 4; mf++) {
        const int row = bm + wm0 + mf * 16 + qr;
#pragma unroll
        for (int nf = 0; nf < 4; nf++) {
            const int col = bn + wn0 + nf * 8 + qc;
            const float b0 = bias[col], b1 = bias[col + 1];
            float2 lo, hi;
            lo.x = acc[mf][nf][0] + b0; lo.y = acc[mf][nf][1] + b1;
            hi.x = acc[mf][nf][2] + b0; hi.y = acc[mf][nf][3] + b1;
            *(float2*)(C + (size_t)row * 512 + col) = lo;
            *(float2*)(C + (size_t)(row + 8) * 512 + col) = hi;
        }
    }
}

// ================= V mean =================
__global__ void vmean_partial(const float* __restrict__ V, float* __restrict__ part) {
    const int b = blockIdx.y, sc = blockIdx.x, c = threadIdx.x;
    const float* p = V + ((size_t)b * S_ + sc * 32) * DM_ + c;
    float s = 0.f;
#pragma unroll 8
    for (int t = 0; t < 32; t++) s += p[(size_t)t * DM_];
    part[((size_t)b * 64 + sc) * DM_ + c] = s;
}

__global__ void vmean_final(const float* __restrict__ part, float* __restrict__ vm) {
    const int b = blockIdx.x, c = threadIdx.x;
    const float* p = part + (size_t)b * 64 * DM_ + c;
    float s = 0.f;
#pragma unroll
    for (int t = 0; t < 64; t++) s += p[(size_t)t * DM_];
    vm[b * DM_ + c] = s * (1.0f / 2048.0f);
}

// ================= HMMA banded attention =================
// block = 64 queries x head x batch; 256 threads (8 warps: 4 m-tiles x 2 n-tiles).
// smem layout (bytes):
//   Q3 @ 0      : 64 rows x 400B   (192 bf16 cols, (qhi,qlo,qhi))
//   K3 @ 25600  : 64 rows x 400B   ((khi,khi,klo)); reused as P3 in AV phase
//   V3 @ 51200  : 64 rows(dims) x 400B ((vhi,vhi,vlo) along j-triplets)
//   S  @ 76800  : 64 x 325 fp32
//   invl @160000: 64 fp32
#define AQ3 0
#define AK3 25600
#define AV3 51200
#define ASF 76800
#define AIL 160000
#define ATT_SMEM 160256

__global__ __launch_bounds__(256, 1) void attn_mma(const float* __restrict__ Q,
                                                   const float* __restrict__ K,
                                                   const float* __restrict__ V,
                                                   const float* __restrict__ VMEAN,
                                                   const int* __restrict__ XLEN,
                                                   float* __restrict__ CTX) {
    extern __shared__ char smc[];
    const uint32_t sb = smem_u32(smc);
    float* Ss = (float*)(smc + ASF);
    float* invl = (float*)(smc + AIL);

    const int tid = threadIdx.x;
    const int wid = tid >> 5, lane = tid & 31;
    const int q0 = blockIdx.x * 64;
    const int h = blockIdx.y;
    const int b = blockIdx.z;
    const int xl = XLEN[b];
    const size_t base = ((size_t)b * S_) * DM_ + h * D_;

    const int wm = (wid & 3) * 16;       // warp m-tile (queries)
    const int wn = (wid >> 2) * 32;      // warp n-tile (keys chunk / dims)
    const int qr = lane >> 2, qc = (lane & 3) * 2;
    const int kbase0 = q0 - 128;

    // ---- build Q3 (once) ----
    {
        const int i = tid >> 2, dg = tid & 3;
        const float* qrow = Q + base + (size_t)(q0 + i) * DM_;
        char* q3row = smc + AQ3 + i * 400;
#pragma unroll
        for (int t = 0; t < 4; t++) {
            const int d0 = dg * 16 + t * 4;
            float4 qv = *(const float4*)(qrow + d0);
            float vv[4] = {qv.x, qv.y, qv.z, qv.w};
#pragma unroll
            for (int u = 0; u < 4; u++) {
                __nv_bfloat16 hi, lo; split2(vv[u], hi, lo);
                __nv_bfloat16* p = (__nv_bfloat16*)(q3row + 6 * (d0 + u));
                p[0] = hi; p[1] = lo; p[2] = hi;
            }
        }
    }

    // ---- phase 1: energies via HMMA, 5 key chunks ----
    for (int c = 0; c < 5; c++) {
        const int kb = kbase0 + c * 64;
        if (c > 0) __syncthreads();  // prev chunk's mma reads of K3 done
        // convert K chunk -> K3
        {
            const int j = tid >> 2, dg = tid & 3;
            const int jabs = kb + j;
            const bool inr = (jabs >= 0) && (jabs < S_);
            const float* krow = K + base + (size_t)jabs * DM_;
            char* k3row = smc + AK3 + j * 400;
#pragma unroll
            for (int t = 0; t < 4; t++) {
                const int d0 = dg * 16 + t * 4;
                float4 kv = inr ? *(const float4*)(krow + d0) : make_float4(0.f, 0.f, 0.f, 0.f);
                float vv[4] = {kv.x, kv.y, kv.z, kv.w};
#pragma unroll
                for (int u = 0; u < 4; u++) {
                    __nv_bfloat16 hi, lo; split2(vv[u], hi, lo);
                    __nv_bfloat16* p = (__nv_bfloat16*)(k3row + 6 * (d0 + u));
                    p[0] = hi; p[1] = hi; p[2] = lo;
                }
            }
        }
        __syncthreads();

        float acc[4][4];
#pragma unroll
        for (int nf = 0; nf < 4; nf++)
#pragma unroll
            for (int u = 0; u < 4; u++) acc[nf][u] = 0.f;

#pragma unroll
        for (int ks = 0; ks < 12; ks++) {
            const int cb = ks * 32 + (lane >> 4) * 16;
            uint32_t a[4];
            ldmx4(a[0], a[1], a[2], a[3], sb + AQ3 + (wm + (lane & 15)) * 400 + cb);
            uint32_t bf[2][4];
#pragma unroll
            for (int nh = 0; nh < 2; nh++) {
                const int r = wn + nh * 16 + (lane & 15);
                ldmx4(bf[nh][0], bf[nh][1], bf[nh][2], bf[nh][3],
                      sb + AK3 + r * 400 + cb);
            }
#pragma unroll
            for (int nf = 0; nf < 4; nf++) {
                const uint32_t b0 = bf[nf >> 1][(nf & 1)];
                const uint32_t b1 = bf[nf >> 1][(nf & 1) + 2];
                mma16816(acc[nf], a, b0, b1);
            }
        }

        // store S fragments with mask+scale
        const int i0 = wm + qr, iabs0 = q0 + i0;
        const int i1 = i0 + 8,  iabs1 = iabs0 + 8;
#pragma unroll
        for (int nf = 0; nf < 4; nf++) {
#pragma unroll
            for (int cc = 0; cc < 2; cc++) {
                const int col = wn + nf * 8 + qc + cc;
                const int jabs = kb + col;
                const bool jok = (jabs >= 0) && (jabs < xl);
                const bool v0 = jok && (jabs - iabs0 <= 128) && (iabs0 - jabs <= 128);
                const bool v1 = jok && (jabs - iabs1 <= 128) && (iabs1 - jabs <= 128);
                Ss[i0 * 325 + c * 64 + col] = v0 ? acc[nf][cc] * 0.125f : -1e30f;
                Ss[i1 * 325 + c * 64 + col] = v1 ? acc[nf][cc + 2] * 0.125f : -1e30f;
            }
        }
    }
    __syncthreads();

    // ---- phase 2: row softmax over 320 keys (8 rows per warp) ----
    {
        for (int rr = 0; rr < 8; rr++) {
            const int i = wid * 8 + rr;
            float* row = Ss + i * 325;
            float vals[10];
            float m = -3.0e38f;
#pragma unroll
            for (int t = 0; t < 10; t++) {
                vals[t] = row[lane + 32 * t];
                m = fmaxf(m, vals[t]);
            }
#pragma unroll
            for (int o = 16; o; o >>= 1) m = fmaxf(m, __shfl_xor_sync(0xffffffffu, m, o));
            float l = 0.f;
#pragma unroll
            for (int t = 0; t < 10; t++) {
                const float p = __expf(vals[t] - m);
                row[lane + 32 * t] = p;
                l += p;
            }
#pragma unroll
            for (int o = 16; o; o >>= 1) l += __shfl_xor_sync(0xffffffffu, l, o);
            if (lane == 0) invl[i] = 1.0f / l;
        }
    }
    __syncthreads();

    // ---- phase 3: AV via HMMA ----
    float oacc[4][4];
#pragma unroll
    for (int nf = 0; nf < 4; nf++)
#pragma unroll
        for (int u = 0; u < 4; u++) oacc[nf][u] = 0.f;

    for (int c = 0; c < 5; c++) {
        const int kb = kbase0 + c * 64;
        // convert P chunk -> P3 (in K3 buffer), V chunk -> V3
        {
            const int row = tid & 63, jg = tid >> 6;
            char* prow = smc + AK3 + row * 400;
            const float* srow = Ss + row * 325 + c * 64 + jg * 16;
#pragma unroll
            for (int jj = 0; jj < 16; jj++) {
                __nv_bfloat16 hi, lo; split2(srow[jj], hi, lo);
                __nv_bfloat16* p = (__nv_bfloat16*)(prow + 6 * (jg * 16 + jj));
                p[0] = hi; p[1] = lo; p[2] = hi;
            }
        }
        {
            const int j = tid >> 2, dg = tid & 3;
            const int jabs = kb + j;
            const bool inr = (jabs >= 0) && (jabs < S_);
            const float* vrow = V + base + (size_t)jabs * DM_;
#pragma unroll
            for (int t = 0; t < 4; t++) {
                const int d0 = dg * 16 + t * 4;
                float4 vv4 = inr ? *(const float4*)(vrow + d0) : make_float4(0.f, 0.f, 0.f, 0.f);
                float vv[4] = {vv4.x, vv4.y, vv4.z, vv4.w};
#pragma unroll
                for (int u = 0; u < 4; u++) {
                    __nv_bfloat16 hi, lo; split2(vv[u], hi, lo);
                    __nv_bfloat16* p = (__nv_bfloat16*)(smc + AV3 + (d0 + u) * 400 + 6 * j);
                    p[0] = hi; p[1] = hi; p[2] = lo;
                }
            }
        }
        __syncthreads();

#pragma unroll
        for (int ks = 0; ks < 12; ks++) {
            const int cb = ks * 32 + (lane >> 4) * 16;
            uint32_t a[4];
            ldmx4(a[0], a[1], a[2], a[3], sb + AK3 + (wm + (lane & 15)) * 400 + cb);
            uint32_t bf[2][4];
#pragma unroll
            for (int nh = 0; nh < 2; nh++) {
                const int r = wn + nh * 16 + (lane & 15);
                ldmx4(bf[nh][0], bf[nh][1], bf[nh][2], bf[nh][3],
                      sb + AV3 + r * 400 + cb);
            }
#pragma unroll
            for (int nf = 0; nf < 4; nf++) {
                const uint32_t b0 = bf[nf >> 1][(nf & 1)];
                const uint32_t b1 = bf[nf >> 1][(nf & 1) + 2];
                mma16816(oacc[nf], a, b0, b1);
            }
        }
        if (c < 4) __syncthreads();  // before overwriting P3/V3
    }

    // ---- final write: normalize, degenerate override ----
    {
        const int i0 = wm + qr;
#pragma unroll
        for (int half = 0; half < 2; half++) {
            const int i = i0 + half * 8;
            const int iabs = q0 + i;
            int lo2 = iabs - 128;
            if (lo2 < 0) lo2 = 0;
            const bool deg = (lo2 >= xl);
            const float il = invl[i];
            float* crow = CTX + base + (size_t)iabs * DM_;
            const float* vm = VMEAN + b * DM_ + h * D_;
#pragma unroll
            for (int nf = 0; nf < 4; nf++) {
                const int col = wn + nf * 8 + qc;
                float2 o;
                o.x = deg ? vm[col]     : oacc[nf][half * 2]     * il;
                o.y = deg ? vm[col + 1] : oacc[nf][half * 2 + 1] * il;
                *(float2*)(crow + col) = o;
            }
        }
    }
}

// ================= launch =================
extern "C" void kernel_launch(void* const* d_in, const int* in_sizes, int n_in,
                              void* d_out, int out_size) {
    const float* x  = (const float*)d_in[0];
    const float* Wq = (const float*)d_in[1];
    const float* bq = (const float*)d_in[2];
    const float* Wk = (const float*)d_in[3];
    const float* bk = (const float*)d_in[4];
    const float* Wv = (const float*)d_in[5];
    const float* bv = (const float*)d_in[6];
    const float* Wo = (const float*)d_in[7];
    const float* bo = (const float*)d_in[8];
    const int* xlen = (const int*)d_in[9];
    float* out = (float*)d_out;

    float *q, *k, *v, *ctx, *part, *vmean;
    __nv_bfloat16 *x3, *w3t;
    cudaGetSymbolAddress((void**)&q, g_q);
    cudaGetSymbolAddress((void**)&k, g_k);
    cudaGetSymbolAddress((void**)&v, g_v);
    cudaGetSymbolAddress((void**)&ctx, g_ctx);
    cudaGetSymbolAddress((void**)&part, g_part);
    cudaGetSymbolAddress((void**)&vmean, g_vmean);
    cudaGetSymbolAddress((void**)&x3, g_x3);
    cudaGetSymbolAddress((void**)&w3t, g_w3t);

    cudaFuncSetAttribute(attn_mma, cudaFuncAttributeMaxDynamicSharedMemorySize, ATT_SMEM);
    cudaFuncSetAttribute(gemm_mma, cudaFuncAttributeMaxDynamicSharedMemorySize, GEMM_SMEM);

    const dim3 gemm_grid(B_ * S_ / 128, DM_ / 128);
    const dim3 wgrid(16, 16), wblk(32, 32);

    split_act3<<<B_ * S_ * 64 / 256, 256>>>(x, x3);
    split_w3<<<wgrid, wblk>>>(Wq, w3t);
    gemm_mma<<<gemm_grid, 256, GEMM_SMEM>>>(x3, w3t, bq, q);
    split_w3<<<wgrid, wblk>>>(Wk, w3t);
    gemm_mma<<<gemm_grid, 256, GEMM_SMEM>>>(x3, w3t, bk, k);
    split_w3<<<wgrid, wblk>>>(Wv, w3t);
    gemm_mma<<<gemm_grid, 256, GEMM_SMEM>>>(x3, w3t, bv, v);

    vmean_partial<<<dim3(64, B_), DM_>>>(v, part);
    vmean_final<<<B_, DM_>>>(part, vmean);

    attn_mma<<<dim3(S_ / 64, H_, B_), 256, ATT_SMEM>>>(q, k, v, vmean, xlen, ctx);

    split_act3<<<B_ * S_ * 64 / 256, 256>>>(ctx, x3);
    split_w3<<<wgrid, wblk>>>(Wo, w3t);
    gemm_mma<<<gemm_grid, 256, GEMM_SMEM>>>(x3, w3t, bo, out);
}